// round 17
// baseline (speedup 1.0000x reference)
#include <cuda_runtime.h>
#include <cuda_bf16.h>
#include <cuda_fp16.h>
#include <cstdint>

#define N 4096
#define FIN 512
#define FOUT 256
#define ALPHA 0.2f
#define JSPLIT 4
#define KCTA (N / JSPLIT)   // 1024
#define NCHUNK (KCTA / 64)  // 16

// ---------------- device scratch ----------------
__device__ float g_fsrc[N];
__device__ float g_fdst[N];
__device__ float g_z[N];
__device__ unsigned g_mask[N * (N / 32)];                    // 2 MB
__device__ __align__(16) __half g_W_hi[FIN * FOUT];          // 256 KB
__device__ __align__(16) __half g_W_lo[FIN * FOUT];          // 256 KB
__device__ __align__(16) __half g_wh_h[N * FOUT];            // 2 MB [j][d] fp16
__device__ __align__(16) __half g_part_h[(size_t)JSPLIT * N * FOUT];  // 8 MB

// ---------------- base-ISA PTX helpers ----------------
__device__ __forceinline__ uint32_t smem_u32(const void* p) {
    uint32_t a;
    asm("{ .reg .u64 t; cvta.to.shared.u64 t, %1; cvt.u32.u64 %0, t; }" : "=r"(a) : "l"(p));
    return a;
}
__device__ __forceinline__ void ldm_x4(uint32_t* r, uint32_t addr) {
    asm volatile("ldmatrix.sync.aligned.m8n8.x4.shared.b16 {%0,%1,%2,%3}, [%4];"
                 : "=r"(r[0]), "=r"(r[1]), "=r"(r[2]), "=r"(r[3]) : "r"(addr));
}
__device__ __forceinline__ void ldm_x4_t(uint32_t* r, uint32_t addr) {
    asm volatile("ldmatrix.sync.aligned.m8n8.x4.trans.shared.b16 {%0,%1,%2,%3}, [%4];"
                 : "=r"(r[0]), "=r"(r[1]), "=r"(r[2]), "=r"(r[3]) : "r"(addr));
}
__device__ __forceinline__ void mma_f16(float* c, const uint32_t* a, const uint32_t* b) {
    asm volatile(
        "mma.sync.aligned.m16n8k16.row.col.f32.f16.f16.f32 "
        "{%0,%1,%2,%3}, {%4,%5,%6,%7}, {%8,%9}, {%0,%1,%2,%3};"
        : "+f"(c[0]), "+f"(c[1]), "+f"(c[2]), "+f"(c[3])
        : "r"(a[0]), "r"(a[1]), "r"(a[2]), "r"(a[3]), "r"(b[0]), "r"(b[1]));
}
#define CP_ASYNC16(dst, src) \
    asm volatile("cp.async.cg.shared.global [%0], [%1], 16;" :: "r"(dst), "l"(src))
#define CP_COMMIT() asm volatile("cp.async.commit_group;" ::: "memory")
#define CP_WAIT0() asm volatile("cp.async.wait_group 0;" ::: "memory")

// ---------------- kernel 0: convert W -> fp16 hi/lo + zero f arrays ---------
__global__ __launch_bounds__(256) void k_cvtW(const float* __restrict__ Wm) {
    const int b = blockIdx.x, t = threadIdx.x;
    if (b < 128) {  // W: 512*256 = 128*1024 floats
        size_t idx = (size_t)b * 1024 + t * 4;
        float4 v = *(const float4*)(Wm + idx);
        __half2 h0 = __floats2half2_rn(v.x, v.y);
        __half2 h1 = __floats2half2_rn(v.z, v.w);
        __half2 l0 = __floats2half2_rn(v.x - __half2float(h0.x), v.y - __half2float(h0.y));
        __half2 l1 = __floats2half2_rn(v.z - __half2float(h1.x), v.w - __half2float(h1.y));
        *(uint2*)(g_W_hi + idx) = make_uint2(*(unsigned*)&h0, *(unsigned*)&h1);
        *(uint2*)(g_W_lo + idx) = make_uint2(*(unsigned*)&l0, *(unsigned*)&l1);
    } else {  // zero g_fsrc / g_fdst / g_z
        float4 z = make_float4(0.f, 0.f, 0.f, 0.f);
#pragma unroll
        for (int u = 0; u < 4; u++) {
            ((float4*)g_fsrc)[t * 4 + u] = z;
            ((float4*)g_fdst)[t * 4 + u] = z;
            ((float4*)g_z)[t * 4 + u] = z;
        }
    }
}

// ---------------- kernel 1: wh GEMM via HMMA, in-kernel h conversion --------
// M=32 per CTA (128 CTAs), N=256, K=512 in 8 chunks of 64. 1024 thr / 32 warps.
// smem: A fp16 resident 32x1040B = 33280 | 2 stages x {BHI 33792 | BLO 33792}
#define WH_A 0
#define WH_B0 33280
#define WH_BSTG 67584
#define SMEM_WH (WH_B0 + 2 * WH_BSTG)  // 168448

__global__ __launch_bounds__(1024, 1) void k_wh_h(const float* __restrict__ hsrc,
                                                  const float* __restrict__ bias,
                                                  const float* __restrict__ a1,
                                                  const float* __restrict__ a2) {
    extern __shared__ char smem[];
    const uint32_t sbase = smem_u32(smem);
    const int t = threadIdx.x, lane = t & 31, warp = t >> 5;
    const int mg = warp & 1, ns = warp >> 1;
    const int i0 = blockIdx.x * 32;

    // ---- prologue: stage h fp32 (32 x 2048B) into B area, convert to A fp16
#pragma unroll
    for (int u = 0; u < 4; u++) {
        int idx = t + 1024 * u;           // 4096 x 16B = 64 KB
        int row = idx >> 7, q = idx & 127;
        CP_ASYNC16(sbase + WH_B0 + row * 2048 + q * 16,
                   (const void*)(hsrc + (size_t)(i0 + row) * FIN + q * 4));
    }
    CP_COMMIT();
    CP_WAIT0();
    __syncthreads();
    {
        const int row = t >> 5, g = t & 31;  // 16 k-values per thread
        const float4* src = (const float4*)(smem + WH_B0 + row * 2048 + g * 64);
        float4 v0 = src[0], v1 = src[1], v2 = src[2], v3 = src[3];
        __half2 p0 = __floats2half2_rn(v0.x, v0.y), p1 = __floats2half2_rn(v0.z, v0.w);
        __half2 p2 = __floats2half2_rn(v1.x, v1.y), p3 = __floats2half2_rn(v1.z, v1.w);
        __half2 p4 = __floats2half2_rn(v2.x, v2.y), p5 = __floats2half2_rn(v2.z, v2.w);
        __half2 p6 = __floats2half2_rn(v3.x, v3.y), p7 = __floats2half2_rn(v3.z, v3.w);
        char* dst = smem + WH_A + row * 1040 + g * 32;
        *(uint4*)dst = make_uint4(*(unsigned*)&p0, *(unsigned*)&p1,
                                  *(unsigned*)&p2, *(unsigned*)&p3);
        *(uint4*)(dst + 16) = make_uint4(*(unsigned*)&p4, *(unsigned*)&p5,
                                         *(unsigned*)&p6, *(unsigned*)&p7);
    }
    __syncthreads();

    auto fill_B = [&](int c2, uint32_t stg) {
        const int k0 = c2 * 64;
#pragma unroll
        for (int u = 0; u < 2; u++) {
            int idx = t + 1024 * u;
            int j = idx >> 5, dq = idx & 31;
            uint32_t dst = stg + j * 528 + dq * 16;
            size_t src = (size_t)(k0 + j) * FOUT + dq * 8;
            CP_ASYNC16(dst, (const void*)(g_W_hi + src));
            CP_ASYNC16(dst + 33792, (const void*)(g_W_lo + src));
        }
    };

    float acc[2][4];
#pragma unroll
    for (int b = 0; b < 2; b++)
#pragma unroll
        for (int c = 0; c < 4; c++) acc[b][c] = 0.f;

    const uint32_t a_base = sbase + WH_A + (mg * 16 + (lane & 15)) * 1040 + (lane >> 4) * 16;
    const uint32_t b_off = (lane & 15) * 528 + (ns * 16 + (lane >> 4) * 8) * 2;

    fill_B(0, sbase + WH_B0);
    CP_COMMIT();
    CP_WAIT0();
    __syncthreads();

#pragma unroll 1
    for (int c = 0; c < 8; c++) {
        const uint32_t stg = sbase + WH_B0 + (uint32_t)(c & 1) * WH_BSTG;
        const uint32_t stg2 = sbase + WH_B0 + (uint32_t)((c & 1) ^ 1) * WH_BSTG;
        if (c + 1 < 8) { fill_B(c + 1, stg2); CP_COMMIT(); }

#pragma unroll
        for (int kk = 0; kk < 4; kk++) {
            uint32_t ah[4], bh[4], bl[4];
            ldm_x4(ah, a_base + c * 128 + kk * 32);
            ldm_x4_t(bh, stg + b_off + kk * 8448);
            ldm_x4_t(bl, stg + 33792 + b_off + kk * 8448);
            mma_f16(acc[0], ah, bh);
            mma_f16(acc[1], ah, bh + 2);
            mma_f16(acc[0], ah, bl);
            mma_f16(acc[1], ah, bl + 2);
        }
        CP_WAIT0();
        __syncthreads();
    }

    // epilogue: bias, fp16 store, f-dot atomics
    const int d0 = ns * 16 + (lane & 3) * 2;
    const int d1 = d0 + 8;
    const int ir = i0 + mg * 16 + (lane >> 2);
    float2 bv0 = *(const float2*)(bias + d0);
    float2 bv1 = *(const float2*)(bias + d1);
    float o00 = acc[0][0] + bv0.x, o01 = acc[0][1] + bv0.y;
    float o10 = acc[1][0] + bv1.x, o11 = acc[1][1] + bv1.y;
    float o20 = acc[0][2] + bv0.x, o21 = acc[0][3] + bv0.y;
    float o30 = acc[1][2] + bv1.x, o31 = acc[1][3] + bv1.y;

    __half2 p;
    p = __floats2half2_rn(o00, o01); *(uint32_t*)(g_wh_h + (size_t)ir * FOUT + d0) = *(uint32_t*)&p;
    p = __floats2half2_rn(o10, o11); *(uint32_t*)(g_wh_h + (size_t)ir * FOUT + d1) = *(uint32_t*)&p;
    p = __floats2half2_rn(o20, o21); *(uint32_t*)(g_wh_h + (size_t)(ir + 8) * FOUT + d0) = *(uint32_t*)&p;
    p = __floats2half2_rn(o30, o31); *(uint32_t*)(g_wh_h + (size_t)(ir + 8) * FOUT + d1) = *(uint32_t*)&p;

    float2 x0 = *(const float2*)(a1 + d0), x1 = *(const float2*)(a1 + d1);
    float2 y0 = *(const float2*)(a2 + d0), y1 = *(const float2*)(a2 + d1);
    float s1 = o00 * x0.x + o01 * x0.y + o10 * x1.x + o11 * x1.y;
    float s2 = o00 * y0.x + o01 * y0.y + o10 * y1.x + o11 * y1.y;
    float s1b = o20 * x0.x + o21 * x0.y + o30 * x1.x + o31 * x1.y;
    float s2b = o20 * y0.x + o21 * y0.y + o30 * y1.x + o31 * y1.y;
#pragma unroll
    for (int off = 1; off <= 2; off <<= 1) {
        s1 += __shfl_xor_sync(0xffffffffu, s1, off);
        s2 += __shfl_xor_sync(0xffffffffu, s2, off);
        s1b += __shfl_xor_sync(0xffffffffu, s1b, off);
        s2b += __shfl_xor_sync(0xffffffffu, s2b, off);
    }
    if ((lane & 3) == 0) {
        atomicAdd(g_fsrc + ir, s1);
        atomicAdd(g_fdst + ir, s2);
        atomicAdd(g_fsrc + ir + 8, s1b);
        atomicAdd(g_fdst + ir + 8, s2b);
    }
}

// ---------------- kernel 2: adj bit-pack (side stream) ----------------------
__global__ __launch_bounds__(256) void k_mask(const int* __restrict__ adj) {
    const int i = blockIdx.x, t = threadIdx.x;
    const int4* arow = (const int4*)(adj + (size_t)i * N);
#pragma unroll
    for (int u = 0; u < 4; u++) {
        int idx = u * 256 + t;
        int4 a = __ldcs(arow + idx);
        unsigned nib = 0;
        if (a.x > 0) nib |= 1u;
        if (a.y > 0) nib |= 2u;
        if (a.z > 0) nib |= 4u;
        if (a.w > 0) nib |= 8u;
        unsigned v = nib << ((t & 7) * 4);
        v |= __shfl_xor_sync(0xffffffffu, v, 1);
        v |= __shfl_xor_sync(0xffffffffu, v, 2);
        v |= __shfl_xor_sync(0xffffffffu, v, 4);
        if ((t & 7) == 0) g_mask[(size_t)i * 128 + u * 32 + (t >> 3)] = v;
    }
}

// ---------------- kernel 4: HMMA attention GEMM, unnormalized + fused Z -----
#define SM_FD 0
#define SM_MASK 4096
#define SM_STG0 20480
#define A_OFF 0
#define B_OFF 18432
#define STG 52224
#define SMEM_AT (SM_STG0 + 2 * STG)  // 124928

__global__ __launch_bounds__(1024, 1) void k_attn_h(const float* __restrict__ ab) {
    extern __shared__ char smem[];
    const uint32_t sbase = smem_u32(smem);
    float* fd_s = (float*)(smem + SM_FD);
    unsigned* mask_s = (unsigned*)(smem + SM_MASK);
    const int t = threadIdx.x;
    const int lane = t & 31, warp = t >> 5;
    const int mw = warp >> 3, nw = warp & 7;
    const int i0 = blockIdx.x * 128;
    const int js = blockIdx.y;
    const int jorg = js * KCTA;

    const int gi = i0 + (t >> 3);
    const float fsi = g_fsrc[gi] + ab[0];
    float zacc = 0.f;

    if (t < 256) *(float4*)(fd_s + t * 4) = *(const float4*)(g_fdst + jorg + t * 4);
#pragma unroll
    for (int u = 0; u < 4; u++) {
        int idx = t + 1024 * u;
        mask_s[idx] = g_mask[(size_t)(i0 + (idx >> 5)) * 128 + js * 32 + (idx & 31)];
    }
    __syncthreads();

    auto fill_B = [&](int c2, uint32_t stg_s) {
        size_t jg = (size_t)jorg + (size_t)c2 * 64;
#pragma unroll
        for (int u = 0; u < 2; u++) {
            int idx = t + 1024 * u;
            int j = idx >> 5, dq = idx & 31;
            uint32_t dst = stg_s + B_OFF + j * 528 + dq * 16;
            size_t src = (jg + j) * FOUT + dq * 8;
            CP_ASYNC16(dst, (const void*)(g_wh_h + src));
        }
    };
    auto fill_A = [&](int c2, char* stgp) {
        const int row = t >> 3, oct = t & 7;
        unsigned w = mask_s[row * 32 + c2 * 2 + (oct >> 2)] >> ((oct & 3) * 8);
        const float* fdp = fd_s + c2 * 64 + oct * 8;
        uint32_t hv[4];
#pragma unroll
        for (int v = 0; v < 8; v += 2) {
            float e0 = 0.f, e1 = 0.f;
            if ((w >> v) & 1u) {
                float x = fsi + fdp[v];
                e0 = __expf(fmaxf(x, ALPHA * x));
            }
            if ((w >> (v + 1)) & 1u) {
                float x = fsi + fdp[v + 1];
                e1 = __expf(fmaxf(x, ALPHA * x));
            }
            zacc += e0 + e1;
            __half2 h2 = __floats2half2_rn(e0, e1);
            hv[v >> 1] = *(uint32_t*)&h2;
        }
        *(uint4*)(stgp + A_OFF + row * 144 + oct * 16) =
            make_uint4(hv[0], hv[1], hv[2], hv[3]);
    };

    float acc[2][4][4];
#pragma unroll
    for (int a = 0; a < 2; a++)
#pragma unroll
        for (int b = 0; b < 4; b++)
#pragma unroll
            for (int c = 0; c < 4; c++) acc[a][b][c] = 0.f;

    const uint32_t a_off = (mw * 32 + (lane & 15)) * 144 + (lane >> 4) * 16;
    const uint32_t b_off = (lane & 15) * 528 + (nw * 32 + (lane >> 4) * 8) * 2;

    fill_B(0, sbase + SM_STG0);
    CP_COMMIT();
    fill_A(0, smem + SM_STG0);
    CP_WAIT0();
    __syncthreads();

#pragma unroll 1
    for (int c = 0; c < NCHUNK; c++) {
        const int s = c & 1;
        const uint32_t stg = SM_STG0 + (uint32_t)s * STG;
        const uint32_t stg2 = SM_STG0 + (uint32_t)(s ^ 1) * STG;
        const uint32_t Aa = sbase + stg + A_OFF;
        const uint32_t Bb = sbase + stg + B_OFF;

        if (c + 1 < NCHUNK) { fill_B(c + 1, sbase + stg2); CP_COMMIT(); }

#pragma unroll
        for (int kk = 0; kk < 4; kk++) {
            uint32_t bh[2][4];
            const uint32_t ao = a_off + kk * 32;
            const uint32_t bo = b_off + kk * 8448;
#pragma unroll
            for (int seg = 0; seg < 2; seg++)
                ldm_x4_t(bh[seg], Bb + bo + seg * 32);
#pragma unroll
            for (int mt = 0; mt < 2; mt++) {
                uint32_t ah[4];
                ldm_x4(ah, Aa + ao + mt * (16 * 144));
#pragma unroll
                for (int nb = 0; nb < 4; nb++) {
                    const uint32_t* bf = &bh[nb >> 1][(nb & 1) * 2];
                    mma_f16(acc[mt][nb], ah, bf);
                }
            }
            if (kk == 0 && c + 1 < NCHUNK) fill_A(c + 1, smem + stg2);
        }

        CP_WAIT0();
        __syncthreads();
    }

#pragma unroll
    for (int off = 4; off; off >>= 1)
        zacc += __shfl_down_sync(0xffffffffu, zacc, off, 8);
    if ((t & 7) == 0) atomicAdd(g_z + gi, zacc);

    __half* base = g_part_h + (size_t)js * ((size_t)N * FOUT);
#pragma unroll
    for (int mt = 0; mt < 2; mt++) {
        int ir = i0 + mw * 32 + mt * 16 + (lane >> 2);
#pragma unroll
        for (int nb = 0; nb < 4; nb++) {
            int d = nw * 32 + nb * 8 + (lane & 3) * 2;
            __half2 p01 = __floats2half2_rn(acc[mt][nb][0], acc[mt][nb][1]);
            __half2 p23 = __floats2half2_rn(acc[mt][nb][2], acc[mt][nb][3]);
            *(uint32_t*)(base + (size_t)ir * FOUT + d) = *(uint32_t*)&p01;
            *(uint32_t*)(base + (size_t)(ir + 8) * FOUT + d) = *(uint32_t*)&p23;
        }
    }
}

// ---------------- kernel 5: combine partials, normalize, elu (MLP) ----------
__global__ __launch_bounds__(256) void k_comb(float* __restrict__ out) {
    const int t = threadIdx.x;
    const size_t stride = (size_t)N * FOUT;
    const size_t base = (size_t)blockIdx.x * 4096 + t * 4;
#pragma unroll
    for (int g = 0; g < 4; g++) {
        const size_t idx = base + g * 1024;
        uint2 u0 = *(const uint2*)(g_part_h + idx);
        uint2 u1 = *(const uint2*)(g_part_h + stride + idx);
        uint2 u2 = *(const uint2*)(g_part_h + 2 * stride + idx);
        uint2 u3 = *(const uint2*)(g_part_h + 3 * stride + idx);
        float zr = g_z[idx >> 8];
        float rz = (zr > 0.f) ? (1.f / zr) : 0.f;
        float2 a0 = __half22float2(*(__half2*)&u0.x), a1 = __half22float2(*(__half2*)&u0.y);
        float2 b0 = __half22float2(*(__half2*)&u1.x), b1 = __half22float2(*(__half2*)&u1.y);
        float2 c0 = __half22float2(*(__half2*)&u2.x), c1 = __half22float2(*(__half2*)&u2.y);
        float2 d0 = __half22float2(*(__half2*)&u3.x), d1 = __half22float2(*(__half2*)&u3.y);
        float o0 = ((a0.x + b0.x) + (c0.x + d0.x)) * rz;
        float o1 = ((a0.y + b0.y) + (c0.y + d0.y)) * rz;
        float o2 = ((a1.x + b1.x) + (c1.x + d1.x)) * rz;
        float o3 = ((a1.y + b1.y) + (c1.y + d1.y)) * rz;
        float4 r;
        r.x = o0 > 0.f ? o0 : (__expf(o0) - 1.f);
        r.y = o1 > 0.f ? o1 : (__expf(o1) - 1.f);
        r.z = o2 > 0.f ? o2 : (__expf(o2) - 1.f);
        r.w = o3 > 0.f ? o3 : (__expf(o3) - 1.f);
        *(float4*)(out + idx) = r;
    }
}

// ---------------- launch: fork-join capture (mask ∥ cvtW→wh) ---------------
extern "C" void kernel_launch(void* const* d_in, const int* in_sizes, int n_in,
                              void* d_out, int out_size) {
    const int* adj = (const int*)d_in[0];
    const float* h = (const float*)d_in[1];
    const float* Wm = (const float*)d_in[2];
    const float* b = (const float*)d_in[3];
    const float* a1 = (const float*)d_in[4];
    const float* a2 = (const float*)d_in[5];
    const float* ab = (const float*)d_in[6];
    float* out = (float*)d_out;

    static bool inited = false;
    static cudaStream_t s2;
    static cudaEvent_t e1, e2;
    if (!inited) {
        cudaFuncSetAttribute(k_attn_h, cudaFuncAttributeMaxDynamicSharedMemorySize, SMEM_AT);
        cudaFuncSetAttribute(k_wh_h, cudaFuncAttributeMaxDynamicSharedMemorySize, SMEM_WH);
        cudaStreamCreateWithFlags(&s2, cudaStreamNonBlocking);
        cudaEventCreateWithFlags(&e1, cudaEventDisableTiming);
        cudaEventCreateWithFlags(&e2, cudaEventDisableTiming);
        inited = true;
    }

    // fork: k_mask (adj bit-pack, DRAM-bound) runs concurrently with cvtW+wh
    cudaEventRecord(e1, 0);
    cudaStreamWaitEvent(s2, e1, 0);
    k_mask<<<N, 256, 0, s2>>>(adj);
    cudaEventRecord(e2, s2);

    k_cvtW<<<129, 256>>>(Wm);
    k_wh_h<<<N / 32, 1024, SMEM_WH>>>(h, b, a1, a2);

    // join: attention needs the mask
    cudaStreamWaitEvent(0, e2, 0);
    k_attn_h<<<dim3(N / 128, JSPLIT), 1024, SMEM_AT>>>(ab);
    k_comb<<<(N * FOUT) / 4096, 256>>>(out);
}